// round 9
// baseline (speedup 1.0000x reference)
#include <cuda_runtime.h>
#include <cuda_bf16.h>
#include <cstdint>

// Problem constants (fixed by the dataset)
#define MAXZ_CAP   95
#define HDIM       128
#define NRAD       6
#define NNODES_CAP 100000
#define TE         16          // edges per tile
#define HS_STRIDE  20          // padded h-tile row (floats): 80B, 16B-aligned, 4-way STS conflict only

// -------- device scratch (no allocations allowed) --------
__device__ float g_T1[MAXZ_CAP * HDIM];   // emb_table @ W_lin[0:128]
__device__ float g_T2[MAXZ_CAP * HDIM];   // emb_table @ W_lin[128:256]
__device__ int   g_cnt[NNODES_CAP];

__device__ __forceinline__ float silu_f(float x) {
    return x * (1.0f / (1.0f + __expf(-x)));
}

// ---------------------------------------------------------------------------
// K0: zero the per-node counters
// ---------------------------------------------------------------------------
__global__ void zero_cnt_kernel(int n) {
    int i = blockIdx.x * blockDim.x + threadIdx.x;
    if (i < n) g_cnt[i] = 0;
}

// ---------------------------------------------------------------------------
// K1: fold the embedding table through the first two 128x128 blocks of W_lin.
// grid = (maxz), block = 128. Thread t computes column t of T1/T2 for row r.
// ---------------------------------------------------------------------------
__global__ void precompute_T_kernel(const float* __restrict__ emb,
                                    const float* __restrict__ Wlin) {
    __shared__ float row[HDIM];
    const int r = blockIdx.x;
    const int t = threadIdx.x;
    row[t] = emb[r * HDIM + t];
    __syncthreads();
    float a1 = 0.0f, a2 = 0.0f;
#pragma unroll 8
    for (int k = 0; k < HDIM; k++) {
        float e = row[k];
        a1 = fmaf(e, Wlin[k * HDIM + t], a1);
        a2 = fmaf(e, Wlin[(HDIM + k) * HDIM + t], a2);
    }
    g_T1[r * HDIM + t] = a1;
    g_T2[r * HDIM + t] = a2;
}

// ---------------------------------------------------------------------------
// K2: main edge kernel.
//   block = 128 threads (thread t owns output column t), tile = 16 edges.
//   smem: W3 [128x128] f32 (64KB) + h tile [128][HS_STRIDE] + small arrays.
//   Inner GEMM uses packed fma.rn.f32x2 (2 edges per instruction).
// ---------------------------------------------------------------------------
__global__ void __launch_bounds__(128)
edge_kernel(const int*   __restrict__ z,
            const float* __restrict__ pos,
            const int*   __restrict__ ei,     // [2,E] flattened: i row then j row
            const float* __restrict__ freq,   // [6]
            const float* __restrict__ Wrbf,   // [6,128]
            const float* __restrict__ brbf,   // [128]
            const float* __restrict__ Wlin,   // [384,128]  (W3 = rows 256..383)
            const float* __restrict__ blin,   // [128]
            float*       __restrict__ out,    // [N,128], pre-zeroed
            int E) {
    extern __shared__ float sm[];
    float* w3s   = sm;                              // 16384 floats (64KB)
    float* hs    = sm + HDIM * HDIM;                // 128 * HS_STRIDE floats
    float* rbf_s = hs + HDIM * HS_STRIDE;           // TE * 6 floats
    int*   zi_s  = (int*)(rbf_s + TE * NRAD);       // TE
    int*   zj_s  = zi_s + TE;                       // TE
    int*   jj_s  = zj_s + TE;                       // TE

    const int t = threadIdx.x;

    // stage W3 into shared memory (coalesced)
    const float* W3 = Wlin + 256 * HDIM;
    for (int idx = t; idx < HDIM * HDIM; idx += 128) w3s[idx] = W3[idx];

    // per-thread constants (this thread's output column)
    float wr[NRAD];
#pragma unroll
    for (int k = 0; k < NRAD; k++) wr[k] = Wrbf[k * HDIM + t];
    const float brt = brbf[t];
    const float blt = blin[t];
    float fr[NRAD];
#pragma unroll
    for (int k = 0; k < NRAD; k++) fr[k] = freq[k];

    const int numTiles = (E + TE - 1) / TE;
    for (int tile = blockIdx.x; tile < numTiles; tile += gridDim.x) {
        __syncthreads();  // also orders the initial w3s fill on first iteration

        // ---- phase 1: per-edge geometry, Bessel RBF, gather indices ----
        if (t < TE) {
            int eidx = tile * TE + t;
            if (eidx < E) {
                int vi = ei[eidx];
                int vj = ei[E + eidx];
                float dx = pos[3 * vi + 0] - pos[3 * vj + 0];
                float dy = pos[3 * vi + 1] - pos[3 * vj + 1];
                float dz = pos[3 * vi + 2] - pos[3 * vj + 2];
                float d  = sqrtf(fmaf(dx, dx, fmaf(dy, dy, dz * dz)));
                float x  = d * 0.2f;  // d / CUTOFF
                float env = 0.0f;
                if (x < 1.0f) {
                    float x2 = x * x, x4 = x2 * x2;
                    float xp0 = x4 * x;    // x^5
                    float xp1 = xp0 * x;   // x^6
                    float xp2 = xp1 * x;   // x^7
                    env = 1.0f / x - 28.0f * xp0 + 48.0f * xp1 - 21.0f * xp2;
                }
#pragma unroll
                for (int k = 0; k < NRAD; k++)
                    rbf_s[t * NRAD + k] = env * sinf(fr[k] * x);
                zi_s[t] = z[vi];
                zj_s[t] = z[vj];
                jj_s[t] = vj;
                atomicAdd(&g_cnt[vj], 1);
            } else {
#pragma unroll
                for (int k = 0; k < NRAD; k++) rbf_s[t * NRAD + k] = 0.0f;
                zi_s[t] = 0; zj_s[t] = 0; jj_s[t] = -1;
            }
        }
        __syncthreads();

        // ---- phase 1b: h_rbf = silu(rbf @ W_rbf + b_rbf) for this column ----
#pragma unroll
        for (int e = 0; e < TE; e++) {
            float v = brt;
#pragma unroll
            for (int k = 0; k < NRAD; k++)
                v = fmaf(rbf_s[e * NRAD + k], wr[k], v);
            hs[t * HS_STRIDE + e] = silu_f(v);
        }
        __syncthreads();

        // ---- phase 2: dot(h[e][:], W3[:, t]) for 16 edges via f32x2 FMA ----
        unsigned long long a0 = 0ull, a1 = 0ull, a2 = 0ull, a3 = 0ull;
        unsigned long long a4 = 0ull, a5 = 0ull, a6 = 0ull, a7 = 0ull;
#pragma unroll 4
        for (int k = 0; k < HDIM; k++) {
            float w = w3s[k * HDIM + t];
            unsigned long long w2;
            asm("mov.b64 %0, {%1, %1};" : "=l"(w2) : "f"(w));
            const float* hk = hs + k * HS_STRIDE;
            ulonglong2 hA = *reinterpret_cast<const ulonglong2*>(hk);
            ulonglong2 hB = *reinterpret_cast<const ulonglong2*>(hk + 4);
            ulonglong2 hC = *reinterpret_cast<const ulonglong2*>(hk + 8);
            ulonglong2 hD = *reinterpret_cast<const ulonglong2*>(hk + 12);
            asm("fma.rn.f32x2 %0, %1, %2, %0;" : "+l"(a0) : "l"(hA.x), "l"(w2));
            asm("fma.rn.f32x2 %0, %1, %2, %0;" : "+l"(a1) : "l"(hA.y), "l"(w2));
            asm("fma.rn.f32x2 %0, %1, %2, %0;" : "+l"(a2) : "l"(hB.x), "l"(w2));
            asm("fma.rn.f32x2 %0, %1, %2, %0;" : "+l"(a3) : "l"(hB.y), "l"(w2));
            asm("fma.rn.f32x2 %0, %1, %2, %0;" : "+l"(a4) : "l"(hC.x), "l"(w2));
            asm("fma.rn.f32x2 %0, %1, %2, %0;" : "+l"(a5) : "l"(hC.y), "l"(w2));
            asm("fma.rn.f32x2 %0, %1, %2, %0;" : "+l"(a6) : "l"(hD.x), "l"(w2));
            asm("fma.rn.f32x2 %0, %1, %2, %0;" : "+l"(a7) : "l"(hD.y), "l"(w2));
        }

        float dot[TE];
        asm("mov.b64 {%0, %1}, %2;" : "=f"(dot[0]),  "=f"(dot[1])  : "l"(a0));
        asm("mov.b64 {%0, %1}, %2;" : "=f"(dot[2]),  "=f"(dot[3])  : "l"(a1));
        asm("mov.b64 {%0, %1}, %2;" : "=f"(dot[4]),  "=f"(dot[5])  : "l"(a2));
        asm("mov.b64 {%0, %1}, %2;" : "=f"(dot[6]),  "=f"(dot[7])  : "l"(a3));
        asm("mov.b64 {%0, %1}, %2;" : "=f"(dot[8]),  "=f"(dot[9])  : "l"(a4));
        asm("mov.b64 {%0, %1}, %2;" : "=f"(dot[10]), "=f"(dot[11]) : "l"(a5));
        asm("mov.b64 {%0, %1}, %2;" : "=f"(dot[12]), "=f"(dot[13]) : "l"(a6));
        asm("mov.b64 {%0, %1}, %2;" : "=f"(dot[14]), "=f"(dot[15]) : "l"(a7));

        // ---- epilogue: add table terms + bias, silu, scatter-add ----
#pragma unroll
        for (int e = 0; e < TE; e++) {
            int vj = jj_s[e];
            if (vj >= 0) {
                float v = dot[e] + blt
                        + g_T1[zi_s[e] * HDIM + t]
                        + g_T2[zj_s[e] * HDIM + t];
                float o = silu_f(v);
                atomicAdd(&out[(size_t)vj * HDIM + t], o);
            }
        }
    }
}

// ---------------------------------------------------------------------------
// K3: scatter-mean finalize: out[n][t] /= max(cnt[n], 1)
// ---------------------------------------------------------------------------
__global__ void finalize_kernel(float* __restrict__ out, int n) {
    int i = blockIdx.x * blockDim.x + threadIdx.x;
    if (i < n * HDIM) {
        float c = (float)g_cnt[i >> 7];
        out[i] = out[i] / fmaxf(c, 1.0f);
    }
}

// ---------------------------------------------------------------------------
// launch
// ---------------------------------------------------------------------------
extern "C" void kernel_launch(void* const* d_in, const int* in_sizes, int n_in,
                              void* d_out, int out_size) {
    const int*   z    = (const int*)  d_in[0];
    const float* pos  = (const float*)d_in[1];
    const int*   ei   = (const int*)  d_in[2];
    const float* freq = (const float*)d_in[3];
    const float* emb  = (const float*)d_in[4];
    const float* Wrbf = (const float*)d_in[5];
    const float* brbf = (const float*)d_in[6];
    const float* Wlin = (const float*)d_in[7];
    const float* blin = (const float*)d_in[8];
    float* out = (float*)d_out;

    const int N    = in_sizes[0];
    const int E    = in_sizes[2] / 2;
    const int maxz = in_sizes[4] / HDIM;

    // smem: W3 (64KB) + h tile + rbf + 3x index arrays
    const size_t smem_bytes =
        (size_t)(HDIM * HDIM + HDIM * HS_STRIDE + TE * NRAD) * sizeof(float)
        + 3 * TE * sizeof(int);

    // idempotent, deterministic, not a stream op — safe under capture
    cudaFuncSetAttribute(edge_kernel,
                         cudaFuncAttributeMaxDynamicSharedMemorySize,
                         (int)smem_bytes);

    // zero output (poisoned to 0xAA by harness) and counters
    cudaMemsetAsync(d_out, 0, (size_t)N * HDIM * sizeof(float), 0);
    zero_cnt_kernel<<<(N + 255) / 256, 256>>>(N);

    // fold embedding through W_lin blocks 1 & 2
    precompute_T_kernel<<<maxz, 128>>>(emb, Wlin);

    // main edge kernel: 3 CTAs/SM target (76.4KB smem each), grid-stride tiles
    const int grid = 444;  // 3 * 148 SMs
    edge_kernel<<<grid, 128, smem_bytes, 0>>>(z, pos, ei, freq, Wrbf, brbf,
                                              Wlin, blin, out, E);

    // divide by counts
    finalize_kernel<<<(N * HDIM + 255) / 256, 256>>>(out, N);
}

// round 10
// speedup vs baseline: 1.0015x; 1.0015x over previous
#include <cuda_runtime.h>
#include <cuda_bf16.h>
#include <cstdint>

// Problem constants (fixed by the dataset)
#define MAXZ_CAP   95
#define HDIM       128
#define NRAD       6
#define NNODES_CAP 100000
#define TE         16          // edges per tile
#define HS_STRIDE  20          // padded h-tile row (floats): 80B, 16B-aligned, 4-way STS conflict only

// -------- device scratch (no allocations allowed) --------
__device__ float g_T1[MAXZ_CAP * HDIM];   // emb_table @ W_lin[0:128]
__device__ float g_T2[MAXZ_CAP * HDIM];   // emb_table @ W_lin[128:256]
__device__ int   g_cnt[NNODES_CAP];

__device__ __forceinline__ float silu_f(float x) {
    return x * (1.0f / (1.0f + __expf(-x)));
}

// ---------------------------------------------------------------------------
// K0: zero the per-node counters
// ---------------------------------------------------------------------------
__global__ void zero_cnt_kernel(int n) {
    int i = blockIdx.x * blockDim.x + threadIdx.x;
    if (i < n) g_cnt[i] = 0;
}

// ---------------------------------------------------------------------------
// K1: fold the embedding table through the first two 128x128 blocks of W_lin.
// grid = (maxz), block = 128. Thread t computes column t of T1/T2 for row r.
// ---------------------------------------------------------------------------
__global__ void precompute_T_kernel(const float* __restrict__ emb,
                                    const float* __restrict__ Wlin) {
    __shared__ float row[HDIM];
    const int r = blockIdx.x;
    const int t = threadIdx.x;
    row[t] = emb[r * HDIM + t];
    __syncthreads();
    float a1 = 0.0f, a2 = 0.0f;
#pragma unroll 8
    for (int k = 0; k < HDIM; k++) {
        float e = row[k];
        a1 = fmaf(e, Wlin[k * HDIM + t], a1);
        a2 = fmaf(e, Wlin[(HDIM + k) * HDIM + t], a2);
    }
    g_T1[r * HDIM + t] = a1;
    g_T2[r * HDIM + t] = a2;
}

// ---------------------------------------------------------------------------
// K2: main edge kernel.
//   block = 128 threads (thread t owns output column t), tile = 16 edges.
//   smem: W3 [128x128] f32 (64KB) + h tile [128][HS_STRIDE] + small arrays.
//   Inner GEMM uses packed fma.rn.f32x2 (2 edges per instruction).
// ---------------------------------------------------------------------------
__global__ void __launch_bounds__(128)
edge_kernel(const int*   __restrict__ z,
            const float* __restrict__ pos,
            const int*   __restrict__ ei,     // [2,E] flattened: i row then j row
            const float* __restrict__ freq,   // [6]
            const float* __restrict__ Wrbf,   // [6,128]
            const float* __restrict__ brbf,   // [128]
            const float* __restrict__ Wlin,   // [384,128]  (W3 = rows 256..383)
            const float* __restrict__ blin,   // [128]
            float*       __restrict__ out,    // [N,128], pre-zeroed
            int E) {
    extern __shared__ float sm[];
    float* w3s   = sm;                              // 16384 floats (64KB)
    float* hs    = sm + HDIM * HDIM;                // 128 * HS_STRIDE floats
    float* rbf_s = hs + HDIM * HS_STRIDE;           // TE * 6 floats
    int*   zi_s  = (int*)(rbf_s + TE * NRAD);       // TE
    int*   zj_s  = zi_s + TE;                       // TE
    int*   jj_s  = zj_s + TE;                       // TE

    const int t = threadIdx.x;

    // stage W3 into shared memory (coalesced)
    const float* W3 = Wlin + 256 * HDIM;
    for (int idx = t; idx < HDIM * HDIM; idx += 128) w3s[idx] = W3[idx];

    // per-thread constants (this thread's output column)
    float wr[NRAD];
#pragma unroll
    for (int k = 0; k < NRAD; k++) wr[k] = Wrbf[k * HDIM + t];
    const float brt = brbf[t];
    const float blt = blin[t];
    float fr[NRAD];
#pragma unroll
    for (int k = 0; k < NRAD; k++) fr[k] = freq[k];

    const int numTiles = (E + TE - 1) / TE;
    for (int tile = blockIdx.x; tile < numTiles; tile += gridDim.x) {
        __syncthreads();  // also orders the initial w3s fill on first iteration

        // ---- phase 1: per-edge geometry, Bessel RBF, gather indices ----
        if (t < TE) {
            int eidx = tile * TE + t;
            if (eidx < E) {
                int vi = ei[eidx];
                int vj = ei[E + eidx];
                float dx = pos[3 * vi + 0] - pos[3 * vj + 0];
                float dy = pos[3 * vi + 1] - pos[3 * vj + 1];
                float dz = pos[3 * vi + 2] - pos[3 * vj + 2];
                float d  = sqrtf(fmaf(dx, dx, fmaf(dy, dy, dz * dz)));
                float x  = d * 0.2f;  // d / CUTOFF
                float env = 0.0f;
                if (x < 1.0f) {
                    float x2 = x * x, x4 = x2 * x2;
                    float xp0 = x4 * x;    // x^5
                    float xp1 = xp0 * x;   // x^6
                    float xp2 = xp1 * x;   // x^7
                    env = 1.0f / x - 28.0f * xp0 + 48.0f * xp1 - 21.0f * xp2;
                }
#pragma unroll
                for (int k = 0; k < NRAD; k++)
                    rbf_s[t * NRAD + k] = env * sinf(fr[k] * x);
                zi_s[t] = z[vi];
                zj_s[t] = z[vj];
                jj_s[t] = vj;
                atomicAdd(&g_cnt[vj], 1);
            } else {
#pragma unroll
                for (int k = 0; k < NRAD; k++) rbf_s[t * NRAD + k] = 0.0f;
                zi_s[t] = 0; zj_s[t] = 0; jj_s[t] = -1;
            }
        }
        __syncthreads();

        // ---- phase 1b: h_rbf = silu(rbf @ W_rbf + b_rbf) for this column ----
#pragma unroll
        for (int e = 0; e < TE; e++) {
            float v = brt;
#pragma unroll
            for (int k = 0; k < NRAD; k++)
                v = fmaf(rbf_s[e * NRAD + k], wr[k], v);
            hs[t * HS_STRIDE + e] = silu_f(v);
        }
        __syncthreads();

        // ---- phase 2: dot(h[e][:], W3[:, t]) for 16 edges via f32x2 FMA ----
        unsigned long long a0 = 0ull, a1 = 0ull, a2 = 0ull, a3 = 0ull;
        unsigned long long a4 = 0ull, a5 = 0ull, a6 = 0ull, a7 = 0ull;
#pragma unroll 4
        for (int k = 0; k < HDIM; k++) {
            float w = w3s[k * HDIM + t];
            unsigned long long w2;
            asm("mov.b64 %0, {%1, %1};" : "=l"(w2) : "f"(w));
            const float* hk = hs + k * HS_STRIDE;
            ulonglong2 hA = *reinterpret_cast<const ulonglong2*>(hk);
            ulonglong2 hB = *reinterpret_cast<const ulonglong2*>(hk + 4);
            ulonglong2 hC = *reinterpret_cast<const ulonglong2*>(hk + 8);
            ulonglong2 hD = *reinterpret_cast<const ulonglong2*>(hk + 12);
            asm("fma.rn.f32x2 %0, %1, %2, %0;" : "+l"(a0) : "l"(hA.x), "l"(w2));
            asm("fma.rn.f32x2 %0, %1, %2, %0;" : "+l"(a1) : "l"(hA.y), "l"(w2));
            asm("fma.rn.f32x2 %0, %1, %2, %0;" : "+l"(a2) : "l"(hB.x), "l"(w2));
            asm("fma.rn.f32x2 %0, %1, %2, %0;" : "+l"(a3) : "l"(hB.y), "l"(w2));
            asm("fma.rn.f32x2 %0, %1, %2, %0;" : "+l"(a4) : "l"(hC.x), "l"(w2));
            asm("fma.rn.f32x2 %0, %1, %2, %0;" : "+l"(a5) : "l"(hC.y), "l"(w2));
            asm("fma.rn.f32x2 %0, %1, %2, %0;" : "+l"(a6) : "l"(hD.x), "l"(w2));
            asm("fma.rn.f32x2 %0, %1, %2, %0;" : "+l"(a7) : "l"(hD.y), "l"(w2));
        }

        float dot[TE];
        asm("mov.b64 {%0, %1}, %2;" : "=f"(dot[0]),  "=f"(dot[1])  : "l"(a0));
        asm("mov.b64 {%0, %1}, %2;" : "=f"(dot[2]),  "=f"(dot[3])  : "l"(a1));
        asm("mov.b64 {%0, %1}, %2;" : "=f"(dot[4]),  "=f"(dot[5])  : "l"(a2));
        asm("mov.b64 {%0, %1}, %2;" : "=f"(dot[6]),  "=f"(dot[7])  : "l"(a3));
        asm("mov.b64 {%0, %1}, %2;" : "=f"(dot[8]),  "=f"(dot[9])  : "l"(a4));
        asm("mov.b64 {%0, %1}, %2;" : "=f"(dot[10]), "=f"(dot[11]) : "l"(a5));
        asm("mov.b64 {%0, %1}, %2;" : "=f"(dot[12]), "=f"(dot[13]) : "l"(a6));
        asm("mov.b64 {%0, %1}, %2;" : "=f"(dot[14]), "=f"(dot[15]) : "l"(a7));

        // ---- epilogue: add table terms + bias, silu, scatter-add ----
#pragma unroll
        for (int e = 0; e < TE; e++) {
            int vj = jj_s[e];
            if (vj >= 0) {
                float v = dot[e] + blt
                        + g_T1[zi_s[e] * HDIM + t]
                        + g_T2[zj_s[e] * HDIM + t];
                float o = silu_f(v);
                atomicAdd(&out[(size_t)vj * HDIM + t], o);
            }
        }
    }
}

// ---------------------------------------------------------------------------
// K3: scatter-mean finalize: out[n][t] /= max(cnt[n], 1)
// ---------------------------------------------------------------------------
__global__ void finalize_kernel(float* __restrict__ out, int n) {
    int i = blockIdx.x * blockDim.x + threadIdx.x;
    if (i < n * HDIM) {
        float c = (float)g_cnt[i >> 7];
        out[i] = out[i] / fmaxf(c, 1.0f);
    }
}

// ---------------------------------------------------------------------------
// launch
// ---------------------------------------------------------------------------
extern "C" void kernel_launch(void* const* d_in, const int* in_sizes, int n_in,
                              void* d_out, int out_size) {
    const int*   z    = (const int*)  d_in[0];
    const float* pos  = (const float*)d_in[1];
    const int*   ei   = (const int*)  d_in[2];
    const float* freq = (const float*)d_in[3];
    const float* emb  = (const float*)d_in[4];
    const float* Wrbf = (const float*)d_in[5];
    const float* brbf = (const float*)d_in[6];
    const float* Wlin = (const float*)d_in[7];
    const float* blin = (const float*)d_in[8];
    float* out = (float*)d_out;

    const int N    = in_sizes[0];
    const int E    = in_sizes[2] / 2;
    const int maxz = in_sizes[4] / HDIM;

    // smem: W3 (64KB) + h tile + rbf + 3x index arrays
    const size_t smem_bytes =
        (size_t)(HDIM * HDIM + HDIM * HS_STRIDE + TE * NRAD) * sizeof(float)
        + 3 * TE * sizeof(int);

    // idempotent, deterministic, not a stream op — safe under capture
    cudaFuncSetAttribute(edge_kernel,
                         cudaFuncAttributeMaxDynamicSharedMemorySize,
                         (int)smem_bytes);

    // zero output (poisoned to 0xAA by harness) and counters
    cudaMemsetAsync(d_out, 0, (size_t)N * HDIM * sizeof(float), 0);
    zero_cnt_kernel<<<(N + 255) / 256, 256>>>(N);

    // fold embedding through W_lin blocks 1 & 2
    precompute_T_kernel<<<maxz, 128>>>(emb, Wlin);

    // main edge kernel: 3 CTAs/SM target (76.4KB smem each), grid-stride tiles
    const int grid = 444;  // 3 * 148 SMs
    edge_kernel<<<grid, 128, smem_bytes, 0>>>(z, pos, ei, freq, Wrbf, brbf,
                                              Wlin, blin, out, E);

    // divide by counts
    finalize_kernel<<<(N * HDIM + 255) / 256, 256>>>(out, N);
}